// round 1
// baseline (speedup 1.0000x reference)
#include <cuda_runtime.h>
#include <cstdint>

#define NQ 16384
#define DMODEL 256
#define H 8
#define DH 32
#define M 2048
#define TOPN 32
#define QB 16
#define CHUNK 128
#define LIST_MAX 256
#define LN_EPS 1e-5f
#define NEG_SLOPE 0.01f

// ---------------- scratch (no cudaMalloc allowed) ----------------
__device__ float g_Q[NQ * DMODEL];
__device__ float g_K[M * DMODEL];
__device__ float g_V[M * DMODEL];
__device__ float g_CTX[NQ * DMODEL];
__device__ float g_ATT[NQ * DMODEL];
__device__ float g_X1[NQ * DMODEL];
__device__ float g_HB[NQ * DMODEL];
__device__ float g_FF[NQ * DMODEL];

// ---------------- helpers ----------------
__device__ __forceinline__ float wredsum(float v) {
    #pragma unroll
    for (int o = 16; o; o >>= 1) v += __shfl_xor_sync(0xffffffffu, v, o);
    return v;
}
__device__ __forceinline__ float wredmax(float v) {
    #pragma unroll
    for (int o = 16; o; o >>= 1) v = fmaxf(v, __shfl_xor_sync(0xffffffffu, v, o));
    return v;
}
// monotonic float <-> uint key
__device__ __forceinline__ unsigned f2k(float f) {
    unsigned u = __float_as_uint(f);
    return (u & 0x80000000u) ? ~u : (u | 0x80000000u);
}
__device__ __forceinline__ float k2f(unsigned k) {
    return (k & 0x80000000u) ? __uint_as_float(k & 0x7fffffffu)
                             : __uint_as_float(~k);
}

// ---------------- SGEMM: C[N,256] = A[N,256] @ W[256,256]^T + bias ----------------
// BM=BN=128, BK=8, 256 threads, 8x8 microtile. ACT=1 -> LeakyReLU epilogue.
template <int ACT>
__global__ __launch_bounds__(256) void sgemm_nt(
    const float* __restrict__ A, const float* __restrict__ W,
    const float* __restrict__ bias, float* __restrict__ C, int N)
{
    __shared__ __align__(16) float As[8 * 128];
    __shared__ __align__(16) float Bs[8 * 128];
    const int tid = threadIdx.x;
    const int m0 = blockIdx.x * 128;
    const int n0 = blockIdx.y * 128;
    const int tr = tid >> 4;       // 0..15
    const int tc = tid & 15;       // 0..15
    const int lr = tid >> 1;       // 0..127
    const int lc = (tid & 1) * 4;  // 0 or 4

    float acc[8][8];
    #pragma unroll
    for (int i = 0; i < 8; ++i)
        #pragma unroll
        for (int j = 0; j < 8; ++j) acc[i][j] = 0.f;

    const float* Ag = A + (size_t)(m0 + lr) * 256 + lc;
    const float* Wg = W + (size_t)(n0 + lr) * 256 + lc;

    for (int k0 = 0; k0 < 256; k0 += 8) {
        float4 a4 = *(const float4*)(Ag + k0);
        float4 w4 = *(const float4*)(Wg + k0);
        __syncthreads();
        As[(lc + 0) * 128 + lr] = a4.x; As[(lc + 1) * 128 + lr] = a4.y;
        As[(lc + 2) * 128 + lr] = a4.z; As[(lc + 3) * 128 + lr] = a4.w;
        Bs[(lc + 0) * 128 + lr] = w4.x; Bs[(lc + 1) * 128 + lr] = w4.y;
        Bs[(lc + 2) * 128 + lr] = w4.z; Bs[(lc + 3) * 128 + lr] = w4.w;
        __syncthreads();
        #pragma unroll
        for (int kk = 0; kk < 8; ++kk) {
            float ra[8], rb[8];
            #pragma unroll
            for (int i = 0; i < 8; i += 4) {
                float4 t = *(const float4*)&As[kk * 128 + tr * 8 + i];
                ra[i] = t.x; ra[i + 1] = t.y; ra[i + 2] = t.z; ra[i + 3] = t.w;
            }
            #pragma unroll
            for (int j = 0; j < 8; j += 4) {
                float4 t = *(const float4*)&Bs[kk * 128 + tc * 8 + j];
                rb[j] = t.x; rb[j + 1] = t.y; rb[j + 2] = t.z; rb[j + 3] = t.w;
            }
            #pragma unroll
            for (int i = 0; i < 8; ++i)
                #pragma unroll
                for (int j = 0; j < 8; ++j) acc[i][j] += ra[i] * rb[j];
        }
    }
    #pragma unroll
    for (int i = 0; i < 8; ++i) {
        int m = m0 + tr * 8 + i;
        #pragma unroll
        for (int j = 0; j < 8; j += 4) {
            int n = n0 + tc * 8 + j;
            float4 o;
            o.x = acc[i][j + 0] + bias[n + 0];
            o.y = acc[i][j + 1] + bias[n + 1];
            o.z = acc[i][j + 2] + bias[n + 2];
            o.w = acc[i][j + 3] + bias[n + 3];
            if (ACT == 1) {
                o.x = o.x >= 0.f ? o.x : NEG_SLOPE * o.x;
                o.y = o.y >= 0.f ? o.y : NEG_SLOPE * o.y;
                o.z = o.z >= 0.f ? o.z : NEG_SLOPE * o.z;
                o.w = o.w >= 0.f ? o.w : NEG_SLOPE * o.w;
            }
            *(float4*)&C[(size_t)m * 256 + n] = o;
        }
    }
}

// ---------------- fused residual-add + LayerNorm ----------------
// out[row] = LN(a[row] + b[row]) * g + be ; one warp per row
__global__ __launch_bounds__(256) void add_ln(
    const float* __restrict__ a, const float* __restrict__ b,
    const float* __restrict__ g, const float* __restrict__ be,
    float* __restrict__ out)
{
    int row = blockIdx.x * 8 + (threadIdx.x >> 5);
    int lane = threadIdx.x & 31;
    const float* ar = a + (size_t)row * DMODEL;
    const float* br = b + (size_t)row * DMODEL;
    float v[8], s = 0.f, sq = 0.f;
    #pragma unroll
    for (int t = 0; t < 8; ++t) {
        int d = lane + 32 * t;
        v[t] = ar[d] + br[d];
        s += v[t]; sq += v[t] * v[t];
    }
    s = wredsum(s); sq = wredsum(sq);
    float mu = s * (1.f / DMODEL);
    float var = sq * (1.f / DMODEL) - mu * mu;
    float r = rsqrtf(var + LN_EPS);
    float* orow = out + (size_t)row * DMODEL;
    #pragma unroll
    for (int t = 0; t < 8; ++t) {
        int d = lane + 32 * t;
        orow[d] = (v[t] - mu) * r * g[d] + be[d];
    }
}

// ---------------- per-query top-32 select + sparse softmax*V ----------------
__device__ __forceinline__ void process_query(
    int qglob, int h, const float* __restrict__ scrow,
    float* __restrict__ lval, int* __restrict__ lidx,
    float lsum, float lsq, float lmx,
    const float* __restrict__ V, float* __restrict__ CTX, int lane)
{
    float sum = wredsum(lsum);
    float sq  = wredsum(lsq);
    float mx  = wredmax(lmx);
    float mu  = sum * (1.f / (float)M);
    float sg  = sqrtf(fmaxf(sq * (1.f / (float)M) - mu * mu, 0.f));

    // find pivot with TOPN <= count(>=pivot) <= LIST_MAX
    float blo = -3.3e38f, bhi = mx;
    float piv = fminf(mu + 1.9f * sg, mx);
    int cnt = 0;
    bool ok = false;
    for (int it = 0; it < 48; ++it) {
        int c = 0;
        for (int i = lane; i < M; i += 32) c += (scrow[i] >= piv) ? 1 : 0;
        c = __reduce_add_sync(0xffffffffu, c);
        cnt = c;
        if (c >= TOPN && c <= LIST_MAX) { ok = true; break; }
        if (c < TOPN) bhi = piv; else blo = piv;
        piv = 0.5f * (blo + bhi);
    }
    if (!ok) piv = blo;  // count(blo) >= TOPN by bracket invariant

    // compact survivors (value, index)
    int base = 0;
    for (int i = lane; i < M; i += 32) {
        float sv = scrow[i];
        bool p = (sv >= piv);
        unsigned bal = __ballot_sync(0xffffffffu, p);
        if (p) {
            int pos = base + __popc(bal & ((1u << lane) - 1u));
            if (pos < LIST_MAX) { lval[pos] = sv; lidx[pos] = i; }
        }
        base += __popc(bal);
    }
    cnt = base < LIST_MAX ? base : LIST_MAX;
    __syncwarp();

    // exact rank-32 value via binary search over monotone keys (tie-exact)
    unsigned kv[LIST_MAX / 32];
    #pragma unroll
    for (int t = 0; t < LIST_MAX / 32; ++t) {
        int e = lane + t * 32;
        kv[t] = (e < cnt) ? f2k(lval[e]) : 0u;
    }
    unsigned lo = 0u, hi = f2k(mx);
    while (lo < hi) {
        unsigned mid = lo + ((hi - lo + 1u) >> 1);
        int c = 0;
        #pragma unroll
        for (int t = 0; t < LIST_MAX / 32; ++t) c += (kv[t] >= mid) ? 1 : 0;
        c = __reduce_add_sync(0xffffffffu, c);
        if (c >= TOPN) lo = mid; else hi = mid - 1u;
    }
    float thr = k2f(lo);

    // sparse softmax * V over survivor list only
    float den = 0.f;
    float cx[32];
    #pragma unroll
    for (int d = 0; d < 32; ++d) cx[d] = 0.f;
    for (int e = lane; e < cnt; e += 32) {
        float sv = lval[e];
        if (sv >= thr) {
            float w = __expf(sv - mx);
            den += w;
            const float4* vp = (const float4*)&V[(size_t)lidx[e] * DMODEL + h * DH];
            #pragma unroll
            for (int t = 0; t < 8; ++t) {
                float4 vv = vp[t];
                cx[4 * t + 0] += w * vv.x; cx[4 * t + 1] += w * vv.y;
                cx[4 * t + 2] += w * vv.z; cx[4 * t + 3] += w * vv.w;
            }
        }
    }
    #pragma unroll
    for (int o = 16; o; o >>= 1) {
        den += __shfl_xor_sync(0xffffffffu, den, o);
        #pragma unroll
        for (int d = 0; d < 32; ++d) cx[d] += __shfl_xor_sync(0xffffffffu, cx[d], o);
    }
    if (lane == 0) {
        float inv = 1.f / den;
        float4* op = (float4*)&CTX[(size_t)qglob * DMODEL + h * DH];
        #pragma unroll
        for (int t = 0; t < 8; ++t)
            op[t] = make_float4(cx[4 * t + 0] * inv, cx[4 * t + 1] * inv,
                                cx[4 * t + 2] * inv, cx[4 * t + 3] * inv);
    }
}

// grid (NQ/QB, H), 256 threads (8 warps, 2 queries/warp)
__global__ __launch_bounds__(256, 1) void attn_kernel(
    const float* __restrict__ Q, const float* __restrict__ K,
    const float* __restrict__ V, float* __restrict__ CTX)
{
    extern __shared__ float sm[];
    float* sc   = sm;                         // QB * M
    float* Ks   = sc + QB * M;                // CHUNK * 33
    float* qs   = Ks + CHUNK * 33;            // QB * 32
    float* lval = qs + QB * 32;               // QB * LIST_MAX
    int*   lidx = (int*)(lval + QB * LIST_MAX);

    const int tid = threadIdx.x, lane = tid & 31, w = tid >> 5;
    const int h = blockIdx.y;
    const int qblock = blockIdx.x * QB;

    for (int i = tid; i < QB * 32; i += 256) {
        int ql = i >> 5, d = i & 31;
        qs[i] = Q[(size_t)(qblock + ql) * DMODEL + h * DH + d];
    }
    __syncthreads();

    const int qa = 2 * w, qb = 2 * w + 1;
    float qra[32], qrb[32];
    #pragma unroll
    for (int d = 0; d < 32; ++d) {
        qra[d] = qs[qa * 32 + d];
        qrb[d] = qs[qb * 32 + d];
    }

    const float scale = 0.17677669529663687f;  // 1/sqrt(32)
    float sum_a = 0.f, sq_a = 0.f, mx_a = -3.3e38f;
    float sum_b = 0.f, sq_b = 0.f, mx_b = -3.3e38f;

    for (int c = 0; c < M / CHUNK; ++c) {
        __syncthreads();
        for (int f = tid; f < CHUNK * 8; f += 256) {
            int key = f >> 3, c4 = f & 7;
            float4 kvv = *(const float4*)&K[(size_t)(c * CHUNK + key) * DMODEL + h * DH + c4 * 4];
            float* dst = &Ks[key * 33 + c4 * 4];
            dst[0] = kvv.x; dst[1] = kvv.y; dst[2] = kvv.z; dst[3] = kvv.w;
        }
        __syncthreads();
        #pragma unroll
        for (int j = 0; j < 4; ++j) {
            int kk = j * 32 + lane;
            const float* kr = &Ks[kk * 33];
            float aa = 0.f, ab = 0.f;
            #pragma unroll
            for (int d = 0; d < 32; ++d) {
                float kvv = kr[d];
                aa += qra[d] * kvv;
                ab += qrb[d] * kvv;
            }
            aa *= scale; ab *= scale;
            sc[qa * M + c * CHUNK + kk] = aa;
            sc[qb * M + c * CHUNK + kk] = ab;
            sum_a += aa; sq_a += aa * aa; mx_a = fmaxf(mx_a, aa);
            sum_b += ab; sq_b += ab * ab; mx_b = fmaxf(mx_b, ab);
        }
    }
    // warp-local phases from here; own warp wrote its own score rows
    process_query(qblock + qa, h, sc + qa * M, lval + qa * LIST_MAX,
                  lidx + qa * LIST_MAX, sum_a, sq_a, mx_a, V, CTX, lane);
    process_query(qblock + qb, h, sc + qb * M, lval + qb * LIST_MAX,
                  lidx + qb * LIST_MAX, sum_b, sq_b, mx_b, V, CTX, lane);
}

// ---------------- launch ----------------
extern "C" void kernel_launch(void* const* d_in, const int* in_sizes, int n_in,
                              void* d_out, int out_size)
{
    const float* x   = (const float*)d_in[0];
    const float* Ep  = (const float*)d_in[1];
    const float* Em  = (const float*)d_in[2];
    const float* Wq  = (const float*)d_in[3];
    const float* bq  = (const float*)d_in[4];
    const float* Wk  = (const float*)d_in[5];
    const float* bk  = (const float*)d_in[6];
    const float* Wv  = (const float*)d_in[7];
    const float* bv  = (const float*)d_in[8];
    const float* Wo  = (const float*)d_in[9];
    const float* bo  = (const float*)d_in[10];
    const float* W1  = (const float*)d_in[11];
    const float* b1  = (const float*)d_in[12];
    const float* W2  = (const float*)d_in[13];
    const float* b2  = (const float*)d_in[14];
    const float* g1  = (const float*)d_in[15];
    const float* be1 = (const float*)d_in[16];
    const float* g2  = (const float*)d_in[17];
    const float* be2 = (const float*)d_in[18];
    float* out = (float*)d_out;

    float *Qp, *Kp, *Vp, *CTXp, *ATTp, *X1p, *Hp, *FFp;
    cudaGetSymbolAddress((void**)&Qp,  g_Q);
    cudaGetSymbolAddress((void**)&Kp,  g_K);
    cudaGetSymbolAddress((void**)&Vp,  g_V);
    cudaGetSymbolAddress((void**)&CTXp, g_CTX);
    cudaGetSymbolAddress((void**)&ATTp, g_ATT);
    cudaGetSymbolAddress((void**)&X1p, g_X1);
    cudaGetSymbolAddress((void**)&Hp,  g_HB);
    cudaGetSymbolAddress((void**)&FFp, g_FF);

    dim3 gq(NQ / 128, 2), gkv(M / 128, 2);
    sgemm_nt<0><<<gq, 256>>>(x, Wq, bq, Qp, NQ);
    sgemm_nt<0><<<gkv, 256>>>(Ep, Wk, bk, Kp, M);
    sgemm_nt<0><<<gkv, 256>>>(Em, Wv, bv, Vp, M);

    size_t smem = (size_t)(QB * M + CHUNK * 33 + QB * 32 + QB * LIST_MAX) * 4
                + (size_t)QB * LIST_MAX * 4;
    cudaFuncSetAttribute(attn_kernel, cudaFuncAttributeMaxDynamicSharedMemorySize, (int)smem);
    attn_kernel<<<dim3(NQ / QB, H), 256, smem>>>(Qp, Kp, Vp, CTXp);

    sgemm_nt<0><<<gq, 256>>>(CTXp, Wo, bo, ATTp, NQ);
    add_ln<<<NQ / 8, 256>>>(x, ATTp, g1, be1, X1p);
    sgemm_nt<1><<<gq, 256>>>(X1p, W1, b1, Hp, NQ);
    sgemm_nt<0><<<gq, 256>>>(Hp, W2, b2, FFp, NQ);
    add_ln<<<NQ / 8, 256>>>(X1p, FFp, g2, be2, out);
}

// round 2
// speedup vs baseline: 1.4884x; 1.4884x over previous
#include <cuda_runtime.h>
#include <cstdint>

#define NQ 16384
#define DMODEL 256
#define H 8
#define DH 32
#define M 2048
#define TOPN 32
#define QB 16
#define CHUNK 128
#define KSZ (CHUNK * 33)
#define LIST_MAX 128
#define LN_EPS 1e-5f
#define NEG_SLOPE 0.01f

// ---------------- scratch (no cudaMalloc allowed) ----------------
__device__ float g_Q[NQ * DMODEL];
__device__ float g_K[M * DMODEL];
__device__ float g_V[M * DMODEL];
__device__ float g_CTX[NQ * DMODEL];
__device__ float g_ATT[NQ * DMODEL];
__device__ float g_X1[NQ * DMODEL];
__device__ float g_HB[NQ * DMODEL];
__device__ float g_FF[NQ * DMODEL];

// ---------------- helpers ----------------
__device__ __forceinline__ float wredsum(float v) {
    #pragma unroll
    for (int o = 16; o; o >>= 1) v += __shfl_xor_sync(0xffffffffu, v, o);
    return v;
}
__device__ __forceinline__ float wredmax(float v) {
    #pragma unroll
    for (int o = 16; o; o >>= 1) v = fmaxf(v, __shfl_xor_sync(0xffffffffu, v, o));
    return v;
}
// monotonic float <-> uint key
__device__ __forceinline__ unsigned f2k(float f) {
    unsigned u = __float_as_uint(f);
    return (u & 0x80000000u) ? ~u : (u | 0x80000000u);
}
__device__ __forceinline__ float k2f(unsigned k) {
    return (k & 0x80000000u) ? __uint_as_float(k & 0x7fffffffu)
                             : __uint_as_float(~k);
}

// ---------------- SGEMM: C[N,256] = A[N,256] @ W[256,256]^T + bias ----------------
template <int ACT>
__global__ __launch_bounds__(256) void sgemm_nt(
    const float* __restrict__ A, const float* __restrict__ W,
    const float* __restrict__ bias, float* __restrict__ C, int N)
{
    __shared__ __align__(16) float As[8 * 128];
    __shared__ __align__(16) float Bs[8 * 128];
    const int tid = threadIdx.x;
    const int m0 = blockIdx.x * 128;
    const int n0 = blockIdx.y * 128;
    const int tr = tid >> 4;
    const int tc = tid & 15;
    const int lr = tid >> 1;
    const int lc = (tid & 1) * 4;

    float acc[8][8];
    #pragma unroll
    for (int i = 0; i < 8; ++i)
        #pragma unroll
        for (int j = 0; j < 8; ++j) acc[i][j] = 0.f;

    const float* Ag = A + (size_t)(m0 + lr) * 256 + lc;
    const float* Wg = W + (size_t)(n0 + lr) * 256 + lc;

    for (int k0 = 0; k0 < 256; k0 += 8) {
        float4 a4 = *(const float4*)(Ag + k0);
        float4 w4 = *(const float4*)(Wg + k0);
        __syncthreads();
        As[(lc + 0) * 128 + lr] = a4.x; As[(lc + 1) * 128 + lr] = a4.y;
        As[(lc + 2) * 128 + lr] = a4.z; As[(lc + 3) * 128 + lr] = a4.w;
        Bs[(lc + 0) * 128 + lr] = w4.x; Bs[(lc + 1) * 128 + lr] = w4.y;
        Bs[(lc + 2) * 128 + lr] = w4.z; Bs[(lc + 3) * 128 + lr] = w4.w;
        __syncthreads();
        #pragma unroll
        for (int kk = 0; kk < 8; ++kk) {
            float ra[8], rb[8];
            #pragma unroll
            for (int i = 0; i < 8; i += 4) {
                float4 t = *(const float4*)&As[kk * 128 + tr * 8 + i];
                ra[i] = t.x; ra[i + 1] = t.y; ra[i + 2] = t.z; ra[i + 3] = t.w;
            }
            #pragma unroll
            for (int j = 0; j < 8; j += 4) {
                float4 t = *(const float4*)&Bs[kk * 128 + tc * 8 + j];
                rb[j] = t.x; rb[j + 1] = t.y; rb[j + 2] = t.z; rb[j + 3] = t.w;
            }
            #pragma unroll
            for (int i = 0; i < 8; ++i)
                #pragma unroll
                for (int j = 0; j < 8; ++j) acc[i][j] += ra[i] * rb[j];
        }
    }
    #pragma unroll
    for (int i = 0; i < 8; ++i) {
        int m = m0 + tr * 8 + i;
        #pragma unroll
        for (int j = 0; j < 8; j += 4) {
            int n = n0 + tc * 8 + j;
            float4 o;
            o.x = acc[i][j + 0] + bias[n + 0];
            o.y = acc[i][j + 1] + bias[n + 1];
            o.z = acc[i][j + 2] + bias[n + 2];
            o.w = acc[i][j + 3] + bias[n + 3];
            if (ACT == 1) {
                o.x = o.x >= 0.f ? o.x : NEG_SLOPE * o.x;
                o.y = o.y >= 0.f ? o.y : NEG_SLOPE * o.y;
                o.z = o.z >= 0.f ? o.z : NEG_SLOPE * o.z;
                o.w = o.w >= 0.f ? o.w : NEG_SLOPE * o.w;
            }
            *(float4*)&C[(size_t)m * 256 + n] = o;
        }
    }
}

// ---------------- fused residual-add + LayerNorm ----------------
__global__ __launch_bounds__(256) void add_ln(
    const float* __restrict__ a, const float* __restrict__ b,
    const float* __restrict__ g, const float* __restrict__ be,
    float* __restrict__ out)
{
    int row = blockIdx.x * 8 + (threadIdx.x >> 5);
    int lane = threadIdx.x & 31;
    const float* ar = a + (size_t)row * DMODEL;
    const float* br = b + (size_t)row * DMODEL;
    float v[8], s = 0.f, sq = 0.f;
    #pragma unroll
    for (int t = 0; t < 8; ++t) {
        int d = lane + 32 * t;
        v[t] = ar[d] + br[d];
        s += v[t]; sq += v[t] * v[t];
    }
    s = wredsum(s); sq = wredsum(sq);
    float mu = s * (1.f / DMODEL);
    float var = sq * (1.f / DMODEL) - mu * mu;
    float r = rsqrtf(var + LN_EPS);
    float* orow = out + (size_t)row * DMODEL;
    #pragma unroll
    for (int t = 0; t < 8; ++t) {
        int d = lane + 32 * t;
        orow[d] = (v[t] - mu) * r * g[d] + be[d];
    }
}

// ---------------- per-query top-32 select + sparse softmax*V (one warp) ----------------
__device__ __forceinline__ void process_query(
    int qglob, int h, const float* __restrict__ scrow,
    float* __restrict__ lval, int* __restrict__ lidx,
    float sum, float sq, float mx,
    const float* __restrict__ V, float* __restrict__ CTX, int lane)
{
    float mu = sum * (1.f / (float)M);
    float sg = sqrtf(fmaxf(sq * (1.f / (float)M) - mu * mu, 0.f));

    // find pivot with TOPN <= count(>=pivot) <= LIST_MAX
    float blo = -3.3e38f, bhi = mx;
    float piv = fminf(mu + 1.9f * sg, mx);
    bool ok = false;
    for (int it = 0; it < 48; ++it) {
        int c = 0;
        #pragma unroll 4
        for (int i = lane; i < M; i += 32) c += (scrow[i] >= piv) ? 1 : 0;
        c = __reduce_add_sync(0xffffffffu, c);
        if (c >= TOPN && c <= LIST_MAX) { ok = true; break; }
        if (c < TOPN) bhi = piv; else blo = piv;
        piv = 0.5f * (blo + bhi);
    }
    if (!ok) piv = blo;  // count(blo) >= TOPN by bracket invariant

    // compact survivors (value, index)
    int base = 0;
    for (int i = lane; i < M; i += 32) {
        float sv = scrow[i];
        bool p = (sv >= piv);
        unsigned bal = __ballot_sync(0xffffffffu, p);
        if (p) {
            int pos = base + __popc(bal & ((1u << lane) - 1u));
            if (pos < LIST_MAX) { lval[pos] = sv; lidx[pos] = i; }
        }
        base += __popc(bal);
    }
    int cnt = base < LIST_MAX ? base : LIST_MAX;
    __syncwarp();

    // exact rank-32 value via binary search over monotone keys (tie-exact)
    unsigned kv[LIST_MAX / 32];
    #pragma unroll
    for (int t = 0; t < LIST_MAX / 32; ++t) {
        int e = lane + t * 32;
        kv[t] = (e < cnt) ? f2k(lval[e]) : 0u;
    }
    unsigned lo = 0u, hi = f2k(mx);
    while (lo < hi) {
        unsigned mid = lo + ((hi - lo + 1u) >> 1);
        int c = 0;
        #pragma unroll
        for (int t = 0; t < LIST_MAX / 32; ++t) c += (kv[t] >= mid) ? 1 : 0;
        c = __reduce_add_sync(0xffffffffu, c);
        if (c >= TOPN) lo = mid; else hi = mid - 1u;
    }
    float thr = k2f(lo);

    // sparse softmax * V: lane owns output dim `lane`; all lanes walk the list.
    // 4-way unrolled accumulators for MLP on the V loads.
    const float* Vh = V + h * DH + lane;
    float den0 = 0.f, den1 = 0.f, den2 = 0.f, den3 = 0.f;
    float cx0 = 0.f, cx1 = 0.f, cx2 = 0.f, cx3 = 0.f;
    int e = 0;
    for (; e + 4 <= cnt; e += 4) {
        float s0 = lval[e], s1 = lval[e + 1], s2 = lval[e + 2], s3 = lval[e + 3];
        int i0 = lidx[e], i1 = lidx[e + 1], i2 = lidx[e + 2], i3 = lidx[e + 3];
        if (s0 >= thr) { float w = __expf(s0 - mx); den0 += w; cx0 += w * Vh[(size_t)i0 * DMODEL]; }
        if (s1 >= thr) { float w = __expf(s1 - mx); den1 += w; cx1 += w * Vh[(size_t)i1 * DMODEL]; }
        if (s2 >= thr) { float w = __expf(s2 - mx); den2 += w; cx2 += w * Vh[(size_t)i2 * DMODEL]; }
        if (s3 >= thr) { float w = __expf(s3 - mx); den3 += w; cx3 += w * Vh[(size_t)i3 * DMODEL]; }
    }
    for (; e < cnt; ++e) {
        float s0 = lval[e];
        if (s0 >= thr) { float w = __expf(s0 - mx); den0 += w; cx0 += w * Vh[(size_t)lidx[e] * DMODEL]; }
    }
    float den = (den0 + den1) + (den2 + den3);
    float cx  = (cx0 + cx1) + (cx2 + cx3);
    CTX[(size_t)qglob * DMODEL + h * DH + lane] = cx / den;
}

// grid (NQ/QB, H), 512 threads = 16 warps.
// Score phase: warp w handles 2 queries ((w&7)*2, +1) over key-half (w>>3),
// with a per-half K chunk buffer (double-buffered by half).
// Process phase: warp q handles query q alone.
__global__ __launch_bounds__(512, 1) void attn_kernel(
    const float* __restrict__ Q, const float* __restrict__ K,
    const float* __restrict__ V, float* __restrict__ CTX)
{
    extern __shared__ float sm[];
    float* sc  = sm;                       // QB * M           (128 KB)
    float* Ks  = sc + QB * M;              // 2 * KSZ          (33 KB)  — aliased by lists later
    float* qs  = Ks + 2 * KSZ;             // QB * 32
    float* st  = qs + QB * 32;             // QB * 2 * 3 (sum, sq, mx partials)
    float* lval = Ks;                      // QB * LIST_MAX    (alias)
    int*   lidx = (int*)(lval + QB * LIST_MAX);

    const int tid = threadIdx.x, lane = tid & 31, w = tid >> 5;
    const int h = blockIdx.y;
    const int qblock = blockIdx.x * QB;
    const int half = w >> 3;
    const int qa = (w & 7) * 2, qb = qa + 1;

    for (int i = tid; i < QB * 32; i += 512) {
        int ql = i >> 5, d = i & 31;
        qs[i] = Q[(size_t)(qblock + ql) * DMODEL + h * DH + d];
    }
    __syncthreads();

    float qra[32], qrb[32];
    #pragma unroll
    for (int d = 0; d < 32; ++d) {
        qra[d] = qs[qa * 32 + d];
        qrb[d] = qs[qb * 32 + d];
    }

    const float scale = 0.17677669529663687f;  // 1/sqrt(32)
    float sum_a = 0.f, sq_a = 0.f, mx_a = -3.3e38f;
    float sum_b = 0.f, sq_b = 0.f, mx_b = -3.3e38f;

    for (int c = 0; c < 8; ++c) {
        __syncthreads();
        // fill both halves' chunks: 2 * 128 keys * 8 float4 = 2048 float4 over 512 threads
        #pragma unroll
        for (int r = 0; r < 4; ++r) {
            int f = tid + 512 * r;
            int buf = f >> 10;
            int key = (f >> 3) & 127;
            int c4 = f & 7;
            int gk = buf * 1024 + c * 128 + key;
            float4 kv4 = *(const float4*)&K[(size_t)gk * DMODEL + h * DH + c4 * 4];
            float* dst = &Ks[buf * KSZ + key * 33 + c4 * 4];
            dst[0] = kv4.x; dst[1] = kv4.y; dst[2] = kv4.z; dst[3] = kv4.w;
        }
        __syncthreads();
        const float* kb = &Ks[half * KSZ];
        const int kbase = half * 1024 + c * 128;
        #pragma unroll
        for (int j = 0; j < 4; ++j) {
            int kk = j * 32 + lane;
            const float* kr = &kb[kk * 33];
            float aa = 0.f, ab = 0.f;
            #pragma unroll
            for (int d = 0; d < 32; ++d) {
                float kvv = kr[d];
                aa += qra[d] * kvv;
                ab += qrb[d] * kvv;
            }
            aa *= scale; ab *= scale;
            sc[qa * M + kbase + kk] = aa;
            sc[qb * M + kbase + kk] = ab;
            sum_a += aa; sq_a += aa * aa; mx_a = fmaxf(mx_a, aa);
            sum_b += ab; sq_b += ab * ab; mx_b = fmaxf(mx_b, ab);
        }
    }

    // combine partial stats: st layout [QB][2][3]
    sum_a = wredsum(sum_a); sq_a = wredsum(sq_a); mx_a = wredmax(mx_a);
    sum_b = wredsum(sum_b); sq_b = wredsum(sq_b); mx_b = wredmax(mx_b);
    if (lane == 0) {
        float* pa = &st[(qa * 2 + half) * 3];
        pa[0] = sum_a; pa[1] = sq_a; pa[2] = mx_a;
        float* pb = &st[(qb * 2 + half) * 3];
        pb[0] = sum_b; pb[1] = sq_b; pb[2] = mx_b;
    }
    __syncthreads();  // scores + stats complete; Ks now dead -> lists alias it

    const int q = w;  // one warp per query
    float sum = st[(q * 2 + 0) * 3 + 0] + st[(q * 2 + 1) * 3 + 0];
    float sq  = st[(q * 2 + 0) * 3 + 1] + st[(q * 2 + 1) * 3 + 1];
    float mx  = fmaxf(st[(q * 2 + 0) * 3 + 2], st[(q * 2 + 1) * 3 + 2]);

    process_query(qblock + q, h, sc + q * M, lval + q * LIST_MAX,
                  lidx + q * LIST_MAX, sum, sq, mx, V, CTX, lane);
}

// ---------------- launch ----------------
extern "C" void kernel_launch(void* const* d_in, const int* in_sizes, int n_in,
                              void* d_out, int out_size)
{
    const float* x   = (const float*)d_in[0];
    const float* Ep  = (const float*)d_in[1];
    const float* Em  = (const float*)d_in[2];
    const float* Wq  = (const float*)d_in[3];
    const float* bq  = (const float*)d_in[4];
    const float* Wk  = (const float*)d_in[5];
    const float* bk  = (const float*)d_in[6];
    const float* Wv  = (const float*)d_in[7];
    const float* bv  = (const float*)d_in[8];
    const float* Wo  = (const float*)d_in[9];
    const float* bo  = (const float*)d_in[10];
    const float* W1  = (const float*)d_in[11];
    const float* b1  = (const float*)d_in[12];
    const float* W2  = (const float*)d_in[13];
    const float* b2  = (const float*)d_in[14];
    const float* g1  = (const float*)d_in[15];
    const float* be1 = (const float*)d_in[16];
    const float* g2  = (const float*)d_in[17];
    const float* be2 = (const float*)d_in[18];
    float* out = (float*)d_out;

    float *Qp, *Kp, *Vp, *CTXp, *ATTp, *X1p, *Hp, *FFp;
    cudaGetSymbolAddress((void**)&Qp,  g_Q);
    cudaGetSymbolAddress((void**)&Kp,  g_K);
    cudaGetSymbolAddress((void**)&Vp,  g_V);
    cudaGetSymbolAddress((void**)&CTXp, g_CTX);
    cudaGetSymbolAddress((void**)&ATTp, g_ATT);
    cudaGetSymbolAddress((void**)&X1p, g_X1);
    cudaGetSymbolAddress((void**)&Hp,  g_HB);
    cudaGetSymbolAddress((void**)&FFp, g_FF);

    dim3 gq(NQ / 128, 2), gkv(M / 128, 2);
    sgemm_nt<0><<<gq, 256>>>(x, Wq, bq, Qp, NQ);
    sgemm_nt<0><<<gkv, 256>>>(Ep, Wk, bk, Kp, M);
    sgemm_nt<0><<<gkv, 256>>>(Em, Wv, bv, Vp, M);

    size_t smem = (size_t)(QB * M + 2 * KSZ + QB * 32 + QB * 2 * 3) * 4;
    cudaFuncSetAttribute(attn_kernel, cudaFuncAttributeMaxDynamicSharedMemorySize, (int)smem);
    attn_kernel<<<dim3(NQ / QB, H), 512, smem>>>(Qp, Kp, Vp, CTXp);

    sgemm_nt<0><<<gq, 256>>>(CTXp, Wo, bo, ATTp, NQ);
    add_ln<<<NQ / 8, 256>>>(x, ATTp, g1, be1, X1p);
    sgemm_nt<1><<<gq, 256>>>(X1p, W1, b1, Hp, NQ);
    sgemm_nt<0><<<gq, 256>>>(Hp, W2, b2, FFp, NQ);
    add_ln<<<NQ / 8, 256>>>(X1p, FFp, g2, be2, out);
}

// round 3
// speedup vs baseline: 1.5039x; 1.0104x over previous
#include <cuda_runtime.h>
#include <cuda_bf16.h>
#include <cstdint>

#define NQ 16384
#define DMODEL 256
#define H 8
#define DH 32
#define M 2048
#define TOPN 32
#define QB 16
#define SCP 17            // sc pitch (floats) over query dim
#define CHUNK 256
#define NCHUNK (M / CHUNK)
#define KBP 40            // K chunk pitch in bf16 halves (80B rows, conflict-free frags)
#define LIST_MAX 128
#define LN_EPS 1e-5f
#define NEG_SLOPE 0.01f

// ---------------- scratch (no cudaMalloc allowed) ----------------
__device__ float g_Q[NQ * DMODEL];
__device__ float g_K[M * DMODEL];
__device__ float g_V[M * DMODEL];
__device__ float g_CTX[NQ * DMODEL];
__device__ float g_ATT[NQ * DMODEL];
__device__ float g_X1[NQ * DMODEL];
__device__ float g_HB[NQ * DMODEL];
__device__ float g_FF[NQ * DMODEL];

// ---------------- helpers ----------------
__device__ __forceinline__ float wredsum(float v) {
    #pragma unroll
    for (int o = 16; o; o >>= 1) v += __shfl_xor_sync(0xffffffffu, v, o);
    return v;
}
__device__ __forceinline__ float wredmax(float v) {
    #pragma unroll
    for (int o = 16; o; o >>= 1) v = fmaxf(v, __shfl_xor_sync(0xffffffffu, v, o));
    return v;
}
__device__ __forceinline__ unsigned f2k(float f) {
    unsigned u = __float_as_uint(f);
    return (u & 0x80000000u) ? ~u : (u | 0x80000000u);
}
__device__ __forceinline__ float k2f(unsigned k) {
    return (k & 0x80000000u) ? __uint_as_float(k & 0x7fffffffu)
                             : __uint_as_float(~k);
}
// bf16 hi/lo split of two floats, packed as .b32 (low half = first element)
__device__ __forceinline__ void split2(float x, float y, unsigned& hi, unsigned& lo) {
    __nv_bfloat16 xh = __float2bfloat16_rn(x);
    __nv_bfloat16 yh = __float2bfloat16_rn(y);
    __nv_bfloat16 xl = __float2bfloat16_rn(x - __bfloat162float(xh));
    __nv_bfloat16 yl = __float2bfloat16_rn(y - __bfloat162float(yh));
    hi = (unsigned)__bfloat16_as_ushort(xh) | ((unsigned)__bfloat16_as_ushort(yh) << 16);
    lo = (unsigned)__bfloat16_as_ushort(xl) | ((unsigned)__bfloat16_as_ushort(yl) << 16);
}
__device__ __forceinline__ void mma16816(float& d0, float& d1, float& d2, float& d3,
    unsigned a0, unsigned a1, unsigned a2, unsigned a3, unsigned b0, unsigned b1) {
    asm volatile("mma.sync.aligned.m16n8k16.row.col.f32.bf16.bf16.f32 "
        "{%0,%1,%2,%3},{%4,%5,%6,%7},{%8,%9},{%0,%1,%2,%3};"
        : "+f"(d0), "+f"(d1), "+f"(d2), "+f"(d3)
        : "r"(a0), "r"(a1), "r"(a2), "r"(a3), "r"(b0), "r"(b1));
}

// ---------------- SGEMM: C[N,256] = A[N,256] @ W[256,256]^T + bias ----------------
template <int ACT>
__global__ __launch_bounds__(256) void sgemm_nt(
    const float* __restrict__ A, const float* __restrict__ W,
    const float* __restrict__ bias, float* __restrict__ C, int N)
{
    __shared__ __align__(16) float As[8 * 128];
    __shared__ __align__(16) float Bs[8 * 128];
    const int tid = threadIdx.x;
    const int m0 = blockIdx.x * 128;
    const int n0 = blockIdx.y * 128;
    const int tr = tid >> 4;
    const int tc = tid & 15;
    const int lr = tid >> 1;
    const int lc = (tid & 1) * 4;

    float acc[8][8];
    #pragma unroll
    for (int i = 0; i < 8; ++i)
        #pragma unroll
        for (int j = 0; j < 8; ++j) acc[i][j] = 0.f;

    const float* Ag = A + (size_t)(m0 + lr) * 256 + lc;
    const float* Wg = W + (size_t)(n0 + lr) * 256 + lc;

    for (int k0 = 0; k0 < 256; k0 += 8) {
        float4 a4 = *(const float4*)(Ag + k0);
        float4 w4 = *(const float4*)(Wg + k0);
        __syncthreads();
        As[(lc + 0) * 128 + lr] = a4.x; As[(lc + 1) * 128 + lr] = a4.y;
        As[(lc + 2) * 128 + lr] = a4.z; As[(lc + 3) * 128 + lr] = a4.w;
        Bs[(lc + 0) * 128 + lr] = w4.x; Bs[(lc + 1) * 128 + lr] = w4.y;
        Bs[(lc + 2) * 128 + lr] = w4.z; Bs[(lc + 3) * 128 + lr] = w4.w;
        __syncthreads();
        #pragma unroll
        for (int kk = 0; kk < 8; ++kk) {
            float ra[8], rb[8];
            #pragma unroll
            for (int i = 0; i < 8; i += 4) {
                float4 t = *(const float4*)&As[kk * 128 + tr * 8 + i];
                ra[i] = t.x; ra[i + 1] = t.y; ra[i + 2] = t.z; ra[i + 3] = t.w;
            }
            #pragma unroll
            for (int j = 0; j < 8; j += 4) {
                float4 t = *(const float4*)&Bs[kk * 128 + tc * 8 + j];
                rb[j] = t.x; rb[j + 1] = t.y; rb[j + 2] = t.z; rb[j + 3] = t.w;
            }
            #pragma unroll
            for (int i = 0; i < 8; ++i)
                #pragma unroll
                for (int j = 0; j < 8; ++j) acc[i][j] += ra[i] * rb[j];
        }
    }
    #pragma unroll
    for (int i = 0; i < 8; ++i) {
        int m = m0 + tr * 8 + i;
        #pragma unroll
        for (int j = 0; j < 8; j += 4) {
            int n = n0 + tc * 8 + j;
            float4 o;
            o.x = acc[i][j + 0] + bias[n + 0];
            o.y = acc[i][j + 1] + bias[n + 1];
            o.z = acc[i][j + 2] + bias[n + 2];
            o.w = acc[i][j + 3] + bias[n + 3];
            if (ACT == 1) {
                o.x = o.x >= 0.f ? o.x : NEG_SLOPE * o.x;
                o.y = o.y >= 0.f ? o.y : NEG_SLOPE * o.y;
                o.z = o.z >= 0.f ? o.z : NEG_SLOPE * o.z;
                o.w = o.w >= 0.f ? o.w : NEG_SLOPE * o.w;
            }
            *(float4*)&C[(size_t)m * 256 + n] = o;
        }
    }
}

// ---------------- fused residual-add + LayerNorm ----------------
__global__ __launch_bounds__(256) void add_ln(
    const float* __restrict__ a, const float* __restrict__ b,
    const float* __restrict__ g, const float* __restrict__ be,
    float* __restrict__ out)
{
    int row = blockIdx.x * 8 + (threadIdx.x >> 5);
    int lane = threadIdx.x & 31;
    const float* ar = a + (size_t)row * DMODEL;
    const float* br = b + (size_t)row * DMODEL;
    float v[8], s = 0.f, sq = 0.f;
    #pragma unroll
    for (int t = 0; t < 8; ++t) {
        int d = lane + 32 * t;
        v[t] = ar[d] + br[d];
        s += v[t]; sq += v[t] * v[t];
    }
    s = wredsum(s); sq = wredsum(sq);
    float mu = s * (1.f / DMODEL);
    float var = sq * (1.f / DMODEL) - mu * mu;
    float r = rsqrtf(var + LN_EPS);
    float* orow = out + (size_t)row * DMODEL;
    #pragma unroll
    for (int t = 0; t < 8; ++t) {
        int d = lane + 32 * t;
        orow[d] = (v[t] - mu) * r * g[d] + be[d];
    }
}

// ---------------- per-query top-32 select + sparse softmax*V (one warp) ----------------
// scq points at sc + q; element i of the score row is scq[i * SCP].
__device__ __forceinline__ void process_query(
    int qglob, int h, const float* __restrict__ scq,
    float* __restrict__ lval, int* __restrict__ lidx,
    const float* __restrict__ V, float* __restrict__ CTX, int lane)
{
    // stats pass
    float sum = 0.f, sq = 0.f, mx = -3.3e38f;
    for (int i = lane; i < M; i += 32) {
        float v = scq[i * SCP];
        sum += v; sq += v * v; mx = fmaxf(mx, v);
    }
    sum = wredsum(sum); sq = wredsum(sq); mx = wredmax(mx);
    float mu = sum * (1.f / (float)M);
    float sg = sqrtf(fmaxf(sq * (1.f / (float)M) - mu * mu, 0.f));

    // find pivot with TOPN <= count(>=pivot) <= LIST_MAX
    float blo = -3.3e38f, bhi = mx;
    float piv = fminf(mu + 1.9f * sg, mx);
    bool ok = false;
    for (int it = 0; it < 48; ++it) {
        int c = 0;
        #pragma unroll 4
        for (int i = lane; i < M; i += 32) c += (scq[i * SCP] >= piv) ? 1 : 0;
        c = __reduce_add_sync(0xffffffffu, c);
        if (c >= TOPN && c <= LIST_MAX) { ok = true; break; }
        if (c < TOPN) bhi = piv; else blo = piv;
        piv = 0.5f * (blo + bhi);
    }
    if (!ok) piv = blo;  // count(blo) >= TOPN by bracket invariant

    // compact survivors (value, index)
    int base = 0;
    for (int i = lane; i < M; i += 32) {
        float sv = scq[i * SCP];
        bool p = (sv >= piv);
        unsigned bal = __ballot_sync(0xffffffffu, p);
        if (p) {
            int pos = base + __popc(bal & ((1u << lane) - 1u));
            if (pos < LIST_MAX) { lval[pos] = sv; lidx[pos] = i; }
        }
        base += __popc(bal);
    }
    int cnt = base < LIST_MAX ? base : LIST_MAX;
    __syncwarp();

    // exact rank-32 value via binary search over monotone keys (tie-exact)
    unsigned kv[LIST_MAX / 32];
    #pragma unroll
    for (int t = 0; t < LIST_MAX / 32; ++t) {
        int e = lane + t * 32;
        kv[t] = (e < cnt) ? f2k(lval[e]) : 0u;
    }
    unsigned lo = 0u, hi = f2k(mx);
    while (lo < hi) {
        unsigned mid = lo + ((hi - lo + 1u) >> 1);
        int c = 0;
        #pragma unroll
        for (int t = 0; t < LIST_MAX / 32; ++t) c += (kv[t] >= mid) ? 1 : 0;
        c = __reduce_add_sync(0xffffffffu, c);
        if (c >= TOPN) lo = mid; else hi = mid - 1u;
    }
    float thr = k2f(lo);

    // sparse softmax * V: lane owns output dim `lane`
    const float* Vh = V + h * DH + lane;
    float den0 = 0.f, den1 = 0.f, den2 = 0.f, den3 = 0.f;
    float cx0 = 0.f, cx1 = 0.f, cx2 = 0.f, cx3 = 0.f;
    int e = 0;
    for (; e + 4 <= cnt; e += 4) {
        float s0 = lval[e], s1 = lval[e + 1], s2 = lval[e + 2], s3 = lval[e + 3];
        int i0 = lidx[e], i1 = lidx[e + 1], i2 = lidx[e + 2], i3 = lidx[e + 3];
        if (s0 >= thr) { float w = __expf(s0 - mx); den0 += w; cx0 += w * Vh[(size_t)i0 * DMODEL]; }
        if (s1 >= thr) { float w = __expf(s1 - mx); den1 += w; cx1 += w * Vh[(size_t)i1 * DMODEL]; }
        if (s2 >= thr) { float w = __expf(s2 - mx); den2 += w; cx2 += w * Vh[(size_t)i2 * DMODEL]; }
        if (s3 >= thr) { float w = __expf(s3 - mx); den3 += w; cx3 += w * Vh[(size_t)i3 * DMODEL]; }
    }
    for (; e < cnt; ++e) {
        float s0 = lval[e];
        if (s0 >= thr) { float w = __expf(s0 - mx); den0 += w; cx0 += w * Vh[(size_t)lidx[e] * DMODEL]; }
    }
    float den = (den0 + den1) + (den2 + den3);
    float cx  = (cx0 + cx1) + (cx2 + cx3);
    CTX[(size_t)qglob * DMODEL + h * DH + lane] = cx / den;
}

// grid (NQ/QB, H), 512 threads = 16 warps.
// Score phase: bf16-split mma.sync (3 MMAs per fragment pair ~= fp32 scores).
// Each chunk = 256 keys in smem (hi/lo bf16, pitch KBP); warp w owns keys
// [w*16, w*16+16) of each chunk (2 n-tiles of 8). Scores stored sc[key][q],
// pitch SCP for conflict-free per-query column scans.
__global__ __launch_bounds__(512, 1) void attn_kernel(
    const float* __restrict__ Q, const float* __restrict__ K,
    const float* __restrict__ V, float* __restrict__ CTX)
{
    extern __shared__ __align__(16) char smraw[];
    float* sc = (float*)smraw;                                // M*SCP floats
    __nv_bfloat16* kh = (__nv_bfloat16*)(sc + M * SCP);       // CHUNK*KBP halves
    __nv_bfloat16* kl = kh + CHUNK * KBP;                     // CHUNK*KBP halves
    float* qs = (float*)(kl + CHUNK * KBP);                   // QB*32 floats
    float* lval = (float*)kh;                                 // alias (score phase done)
    int*   lidx = (int*)(lval + QB * LIST_MAX);

    const int tid = threadIdx.x, lane = tid & 31, w = tid >> 5;
    const int h = blockIdx.y;
    const int qblock = blockIdx.x * QB;
    const int g = lane >> 2, tq = lane & 3;

    // load Q tile, scaled by 1/sqrt(DH)
    const float scale = 0.17677669529663687f;
    for (int i = tid; i < QB * 32; i += 512) {
        int ql = i >> 5, d = i & 31;
        qs[i] = Q[(size_t)(qblock + ql) * DMODEL + h * DH + d] * scale;
    }
    __syncthreads();

    // build A fragments (bf16 hi/lo); rows = queries, k = dims
    unsigned ah[2][4], al[2][4];
    #pragma unroll
    for (int s = 0; s < 2; ++s) {
        int cb = s * 16 + tq * 2;
        split2(qs[g * 32 + cb],           qs[g * 32 + cb + 1],           ah[s][0], al[s][0]);
        split2(qs[(g + 8) * 32 + cb],     qs[(g + 8) * 32 + cb + 1],     ah[s][1], al[s][1]);
        split2(qs[g * 32 + cb + 8],       qs[g * 32 + cb + 9],           ah[s][2], al[s][2]);
        split2(qs[(g + 8) * 32 + cb + 8], qs[(g + 8) * 32 + cb + 9],     ah[s][3], al[s][3]);
    }

    // K streaming: thread t loads key (t>>1), dim half (t&1)*16 .. +15
    const int keyt = tid >> 1;
    const int doff = (tid & 1) * 16;
    const float* Kg = K + h * DH + doff;

    float4 p[4];
    {
        const float* src = Kg + (size_t)keyt * DMODEL;
        #pragma unroll
        for (int j = 0; j < 4; ++j) p[j] = *(const float4*)(src + 4 * j);
    }

    #pragma unroll 1
    for (int c = 0; c < NCHUNK; ++c) {
        __syncthreads();  // previous chunk's compute done; Kb free
        unsigned hh[8], ll[8];
        #pragma unroll
        for (int j = 0; j < 4; ++j) {
            split2(p[j].x, p[j].y, hh[2 * j],     ll[2 * j]);
            split2(p[j].z, p[j].w, hh[2 * j + 1], ll[2 * j + 1]);
        }
        *(uint4*)&kh[keyt * KBP + doff]     = make_uint4(hh[0], hh[1], hh[2], hh[3]);
        *(uint4*)&kh[keyt * KBP + doff + 8] = make_uint4(hh[4], hh[5], hh[6], hh[7]);
        *(uint4*)&kl[keyt * KBP + doff]     = make_uint4(ll[0], ll[1], ll[2], ll[3]);
        *(uint4*)&kl[keyt * KBP + doff + 8] = make_uint4(ll[4], ll[5], ll[6], ll[7]);
        __syncthreads();  // Kb ready

        if (c + 1 < NCHUNK) {  // prefetch next chunk while computing this one
            const float* src = Kg + (size_t)((c + 1) * CHUNK + keyt) * DMODEL;
            #pragma unroll
            for (int j = 0; j < 4; ++j) p[j] = *(const float4*)(src + 4 * j);
        }

        #pragma unroll
        for (int nt = 0; nt < 2; ++nt) {
            float c0 = 0.f, c1 = 0.f, c2 = 0.f, c3 = 0.f;
            int krow = (w * 16 + nt * 8 + g) * KBP;
            #pragma unroll
            for (int s = 0; s < 2; ++s) {
                int ko = s * 16 + tq * 2;
                unsigned b0h = *(const unsigned*)&kh[krow + ko];
                unsigned b1h = *(const unsigned*)&kh[krow + ko + 8];
                unsigned b0l = *(const unsigned*)&kl[krow + ko];
                unsigned b1l = *(const unsigned*)&kl[krow + ko + 8];
                mma16816(c0, c1, c2, c3, ah[s][0], ah[s][1], ah[s][2], ah[s][3], b0h, b1h);
                mma16816(c0, c1, c2, c3, ah[s][0], ah[s][1], ah[s][2], ah[s][3], b0l, b1l);
                mma16816(c0, c1, c2, c3, al[s][0], al[s][1], al[s][2], al[s][3], b0h, b1h);
            }
            int gk = c * CHUNK + w * 16 + nt * 8 + tq * 2;
            sc[gk * SCP + g]           = c0;  // C[row=q=g][col=key]
            sc[(gk + 1) * SCP + g]     = c1;
            sc[gk * SCP + g + 8]       = c2;
            sc[(gk + 1) * SCP + g + 8] = c3;
        }
    }
    __syncthreads();  // all scores written; Kb dead -> survivor lists alias it

    process_query(qblock + w, h, sc + w, lval + w * LIST_MAX,
                  lidx + w * LIST_MAX, V, CTX, lane);
}

// ---------------- launch ----------------
extern "C" void kernel_launch(void* const* d_in, const int* in_sizes, int n_in,
                              void* d_out, int out_size)
{
    const float* x   = (const float*)d_in[0];
    const float* Ep  = (const float*)d_in[1];
    const float* Em  = (const float*)d_in[2];
    const float* Wq  = (const float*)d_in[3];
    const float* bq  = (const float*)d_in[4];
    const float* Wk  = (const float*)d_in[5];
    const float* bk  = (const float*)d_in[6];
    const float* Wv  = (const float*)d_in[7];
    const float* bv  = (const float*)d_in[8];
    const float* Wo  = (const float*)d_in[9];
    const float* bo  = (const float*)d_in[10];
    const float* W1  = (const float*)d_in[11];
    const float* b1  = (const float*)d_in[12];
    const float* W2  = (const float*)d_in[13];
    const float* b2  = (const float*)d_in[14];
    const float* g1  = (const float*)d_in[15];
    const float* be1 = (const float*)d_in[16];
    const float* g2  = (const float*)d_in[17];
    const float* be2 = (const float*)d_in[18];
    float* out = (float*)d_out;

    float *Qp, *Kp, *Vp, *CTXp, *ATTp, *X1p, *Hp, *FFp;
    cudaGetSymbolAddress((void**)&Qp,  g_Q);
    cudaGetSymbolAddress((void**)&Kp,  g_K);
    cudaGetSymbolAddress((void**)&Vp,  g_V);
    cudaGetSymbolAddress((void**)&CTXp, g_CTX);
    cudaGetSymbolAddress((void**)&ATTp, g_ATT);
    cudaGetSymbolAddress((void**)&X1p, g_X1);
    cudaGetSymbolAddress((void**)&Hp,  g_HB);
    cudaGetSymbolAddress((void**)&FFp, g_FF);

    dim3 gq(NQ / 128, 2), gkv(M / 128, 2);
    sgemm_nt<0><<<gq, 256>>>(x, Wq, bq, Qp, NQ);
    sgemm_nt<0><<<gkv, 256>>>(Ep, Wk, bk, Kp, M);
    sgemm_nt<0><<<gkv, 256>>>(Em, Wv, bv, Vp, M);

    size_t smem = (size_t)M * SCP * 4 + 2 * (size_t)CHUNK * KBP * 2 + QB * 32 * 4;
    cudaFuncSetAttribute(attn_kernel, cudaFuncAttributeMaxDynamicSharedMemorySize, (int)smem);
    attn_kernel<<<dim3(NQ / QB, H), 512, smem>>>(Qp, Kp, Vp, CTXp);

    sgemm_nt<0><<<gq, 256>>>(CTXp, Wo, bo, ATTp, NQ);
    add_ln<<<NQ / 8, 256>>>(x, ATTp, g1, be1, X1p);
    sgemm_nt<1><<<gq, 256>>>(X1p, W1, b1, Hp, NQ);
    sgemm_nt<0><<<gq, 256>>>(Hp, W2, b2, FFp, NQ);
    add_ln<<<NQ / 8, 256>>>(X1p, FFp, g2, be2, out);
}

// round 4
// speedup vs baseline: 1.8848x; 1.2533x over previous
#include <cuda_runtime.h>
#include <cuda_bf16.h>
#include <cstdint>

#define NQ 16384
#define DMODEL 256
#define H 8
#define DH 32
#define M 2048
#define TOPN 32
#define QB 16
#define SCP 17            // sc pitch (floats) over query dim
#define CHUNK 256
#define NCHUNK (M / CHUNK)
#define KBP 72            // K chunk row pitch in bf16 halves (144B rows)
#define LIST_MAX 128
#define LN_EPS 1e-5f
#define NEG_SLOPE 0.01f

// ---------------- scratch (no cudaMalloc allowed) ----------------
__device__ float g_Q[NQ * DMODEL];
__device__ float g_K[M * DMODEL];
__device__ float g_V[M * DMODEL];
__device__ float g_CTX[NQ * DMODEL];
__device__ float g_ATT[NQ * DMODEL];
__device__ float g_X1[NQ * DMODEL];
__device__ float g_HB[NQ * DMODEL];
__device__ float g_FF[NQ * DMODEL];
__device__ __nv_bfloat16 g_Kc[H * M * 64];   // per head/key: 32 hi + 32 lo bf16

// ---------------- helpers ----------------
__device__ __forceinline__ float wredsum(float v) {
    #pragma unroll
    for (int o = 16; o; o >>= 1) v += __shfl_xor_sync(0xffffffffu, v, o);
    return v;
}
__device__ __forceinline__ float wredmax(float v) {
    #pragma unroll
    for (int o = 16; o; o >>= 1) v = fmaxf(v, __shfl_xor_sync(0xffffffffu, v, o));
    return v;
}
__device__ __forceinline__ unsigned f2k(float f) {
    unsigned u = __float_as_uint(f);
    return (u & 0x80000000u) ? ~u : (u | 0x80000000u);
}
__device__ __forceinline__ float k2f(unsigned k) {
    return (k & 0x80000000u) ? __uint_as_float(k & 0x7fffffffu)
                             : __uint_as_float(~k);
}
__device__ __forceinline__ void split2(float x, float y, unsigned& hi, unsigned& lo) {
    __nv_bfloat16 xh = __float2bfloat16_rn(x);
    __nv_bfloat16 yh = __float2bfloat16_rn(y);
    __nv_bfloat16 xl = __float2bfloat16_rn(x - __bfloat162float(xh));
    __nv_bfloat16 yl = __float2bfloat16_rn(y - __bfloat162float(yh));
    hi = (unsigned)__bfloat16_as_ushort(xh) | ((unsigned)__bfloat16_as_ushort(yh) << 16);
    lo = (unsigned)__bfloat16_as_ushort(xl) | ((unsigned)__bfloat16_as_ushort(yl) << 16);
}
__device__ __forceinline__ void mma16816(float& d0, float& d1, float& d2, float& d3,
    unsigned a0, unsigned a1, unsigned a2, unsigned a3, unsigned b0, unsigned b1) {
    asm volatile("mma.sync.aligned.m16n8k16.row.col.f32.bf16.bf16.f32 "
        "{%0,%1,%2,%3},{%4,%5,%6,%7},{%8,%9},{%0,%1,%2,%3};"
        : "+f"(d0), "+f"(d1), "+f"(d2), "+f"(d3)
        : "r"(a0), "r"(a1), "r"(a2), "r"(a3), "r"(b0), "r"(b1));
}
__device__ __forceinline__ void cpa16(unsigned dst, const void* src) {
    asm volatile("cp.async.cg.shared.global [%0], [%1], 16;" :: "r"(dst), "l"(src));
}
#define CPA_COMMIT() asm volatile("cp.async.commit_group;")
#define CPA_WAIT(n)  asm volatile("cp.async.wait_group %0;" :: "n"(n))

// ---------------- K pre-conversion: fp32 -> bf16 hi/lo ----------------
__global__ __launch_bounds__(256) void convK(const float* __restrict__ K,
                                             __nv_bfloat16* __restrict__ Kc)
{
    int t = blockIdx.x * 256 + threadIdx.x;   // t < M*H
    int key = t >> 3, h = t & 7;
    const float* src = K + (size_t)key * DMODEL + h * DH;
    __nv_bfloat16* dst = Kc + ((size_t)h * M + key) * 64;
    #pragma unroll
    for (int d = 0; d < 32; d += 2) {
        unsigned hi, lo;
        split2(src[d], src[d + 1], hi, lo);
        *(unsigned*)&dst[d]      = hi;
        *(unsigned*)&dst[32 + d] = lo;
    }
}

// ---------------- SGEMM: C[N,256] = A[N,256] @ W[256,256]^T + bias ----------------
template <int ACT>
__global__ __launch_bounds__(256) void sgemm_nt(
    const float* __restrict__ A, const float* __restrict__ W,
    const float* __restrict__ bias, float* __restrict__ C, int N)
{
    __shared__ __align__(16) float As[8 * 128];
    __shared__ __align__(16) float Bs[8 * 128];
    const int tid = threadIdx.x;
    const int m0 = blockIdx.x * 128;
    const int n0 = blockIdx.y * 128;
    const int tr = tid >> 4;
    const int tc = tid & 15;
    const int lr = tid >> 1;
    const int lc = (tid & 1) * 4;

    float acc[8][8];
    #pragma unroll
    for (int i = 0; i < 8; ++i)
        #pragma unroll
        for (int j = 0; j < 8; ++j) acc[i][j] = 0.f;

    const float* Ag = A + (size_t)(m0 + lr) * 256 + lc;
    const float* Wg = W + (size_t)(n0 + lr) * 256 + lc;

    for (int k0 = 0; k0 < 256; k0 += 8) {
        float4 a4 = *(const float4*)(Ag + k0);
        float4 w4 = *(const float4*)(Wg + k0);
        __syncthreads();
        As[(lc + 0) * 128 + lr] = a4.x; As[(lc + 1) * 128 + lr] = a4.y;
        As[(lc + 2) * 128 + lr] = a4.z; As[(lc + 3) * 128 + lr] = a4.w;
        Bs[(lc + 0) * 128 + lr] = w4.x; Bs[(lc + 1) * 128 + lr] = w4.y;
        Bs[(lc + 2) * 128 + lr] = w4.z; Bs[(lc + 3) * 128 + lr] = w4.w;
        __syncthreads();
        #pragma unroll
        for (int kk = 0; kk < 8; ++kk) {
            float ra[8], rb[8];
            #pragma unroll
            for (int i = 0; i < 8; i += 4) {
                float4 t = *(const float4*)&As[kk * 128 + tr * 8 + i];
                ra[i] = t.x; ra[i + 1] = t.y; ra[i + 2] = t.z; ra[i + 3] = t.w;
            }
            #pragma unroll
            for (int j = 0; j < 8; j += 4) {
                float4 t = *(const float4*)&Bs[kk * 128 + tc * 8 + j];
                rb[j] = t.x; rb[j + 1] = t.y; rb[j + 2] = t.z; rb[j + 3] = t.w;
            }
            #pragma unroll
            for (int i = 0; i < 8; ++i)
                #pragma unroll
                for (int j = 0; j < 8; ++j) acc[i][j] += ra[i] * rb[j];
        }
    }
    #pragma unroll
    for (int i = 0; i < 8; ++i) {
        int m = m0 + tr * 8 + i;
        #pragma unroll
        for (int j = 0; j < 8; j += 4) {
            int n = n0 + tc * 8 + j;
            float4 o;
            o.x = acc[i][j + 0] + bias[n + 0];
            o.y = acc[i][j + 1] + bias[n + 1];
            o.z = acc[i][j + 2] + bias[n + 2];
            o.w = acc[i][j + 3] + bias[n + 3];
            if (ACT == 1) {
                o.x = o.x >= 0.f ? o.x : NEG_SLOPE * o.x;
                o.y = o.y >= 0.f ? o.y : NEG_SLOPE * o.y;
                o.z = o.z >= 0.f ? o.z : NEG_SLOPE * o.z;
                o.w = o.w >= 0.f ? o.w : NEG_SLOPE * o.w;
            }
            *(float4*)&C[(size_t)m * 256 + n] = o;
        }
    }
}

// ---------------- fused residual-add + LayerNorm ----------------
__global__ __launch_bounds__(256) void add_ln(
    const float* __restrict__ a, const float* __restrict__ b,
    const float* __restrict__ g, const float* __restrict__ be,
    float* __restrict__ out)
{
    int row = blockIdx.x * 8 + (threadIdx.x >> 5);
    int lane = threadIdx.x & 31;
    const float* ar = a + (size_t)row * DMODEL;
    const float* br = b + (size_t)row * DMODEL;
    float v[8], s = 0.f, sq = 0.f;
    #pragma unroll
    for (int t = 0; t < 8; ++t) {
        int d = lane + 32 * t;
        v[t] = ar[d] + br[d];
        s += v[t]; sq += v[t] * v[t];
    }
    s = wredsum(s); sq = wredsum(sq);
    float mu = s * (1.f / DMODEL);
    float var = sq * (1.f / DMODEL) - mu * mu;
    float r = rsqrtf(var + LN_EPS);
    float* orow = out + (size_t)row * DMODEL;
    #pragma unroll
    for (int t = 0; t < 8; ++t) {
        int d = lane + 32 * t;
        orow[d] = (v[t] - mu) * r * g[d] + be[d];
    }
}

// ---------------- per-query top-32 select + sparse softmax*V (one warp) ----------------
// scq = sc + q; element i at scq[i*SCP]. Stats (sum,sq,mx) precomputed.
__device__ __forceinline__ void process_query(
    int qglob, int h, const float* __restrict__ scq,
    float* __restrict__ lval, int* __restrict__ lidx,
    float sum, float sq, float mx,
    const float* __restrict__ V, float* __restrict__ CTX, int lane)
{
    float mu = sum * (1.f / (float)M);
    float sg = sqrtf(fmaxf(sq * (1.f / (float)M) - mu * mu, 0.f));

    // find pivot with TOPN <= count(>=pivot) <= LIST_MAX; track per-lane count
    float blo = -3.3e38f, bhi = mx;
    float piv = fminf(mu + 1.9f * sg, mx);
    int myc = 0;
    bool ok = false;
    for (int it = 0; it < 48; ++it) {
        myc = 0;
        #pragma unroll 4
        for (int i = lane; i < M; i += 32) myc += (scq[i * SCP] >= piv) ? 1 : 0;
        int c = __reduce_add_sync(0xffffffffu, myc);
        if (c >= TOPN && c <= LIST_MAX) { ok = true; break; }
        if (c < TOPN) bhi = piv; else blo = piv;
        piv = 0.5f * (blo + bhi);
    }
    if (!ok) {  // bracket invariant: count(blo) >= TOPN
        piv = blo;
        myc = 0;
        #pragma unroll 4
        for (int i = lane; i < M; i += 32) myc += (scq[i * SCP] >= piv) ? 1 : 0;
    }
    int total = __reduce_add_sync(0xffffffffu, myc);

    // de-chained compaction: exclusive lane scan, then independent stores
    int off = myc;
    #pragma unroll
    for (int o = 1; o < 32; o <<= 1) {
        int t = __shfl_up_sync(0xffffffffu, off, o);
        if (lane >= o) off += t;
    }
    off -= myc;  // exclusive prefix
    int p = off;
    #pragma unroll 4
    for (int i = lane; i < M; i += 32) {
        float sv = scq[i * SCP];
        if (sv >= piv) {
            if (p < LIST_MAX) { lval[p] = sv; lidx[p] = i; }
            ++p;
        }
    }
    int cnt = total < LIST_MAX ? total : LIST_MAX;
    __syncwarp();

    // exact rank-32 value via binary search over monotone keys (tie-exact)
    unsigned kv[LIST_MAX / 32];
    #pragma unroll
    for (int t = 0; t < LIST_MAX / 32; ++t) {
        int e = lane + t * 32;
        kv[t] = (e < cnt) ? f2k(lval[e]) : 0u;
    }
    unsigned lo = 0u, hi = f2k(mx);
    while (lo < hi) {
        unsigned mid = lo + ((hi - lo + 1u) >> 1);
        int c = 0;
        #pragma unroll
        for (int t = 0; t < LIST_MAX / 32; ++t) c += (kv[t] >= mid) ? 1 : 0;
        c = __reduce_add_sync(0xffffffffu, c);
        if (c >= TOPN) lo = mid; else hi = mid - 1u;
    }
    float thr = k2f(lo);

    // sparse softmax * V: lane owns output dim `lane`
    const float* Vh = V + h * DH + lane;
    float den0 = 0.f, den1 = 0.f, den2 = 0.f, den3 = 0.f;
    float cx0 = 0.f, cx1 = 0.f, cx2 = 0.f, cx3 = 0.f;
    int e = 0;
    for (; e + 4 <= cnt; e += 4) {
        float s0 = lval[e], s1 = lval[e + 1], s2 = lval[e + 2], s3 = lval[e + 3];
        int i0 = lidx[e], i1 = lidx[e + 1], i2 = lidx[e + 2], i3 = lidx[e + 3];
        if (s0 >= thr) { float w = __expf(s0 - mx); den0 += w; cx0 += w * Vh[(size_t)i0 * DMODEL]; }
        if (s1 >= thr) { float w = __expf(s1 - mx); den1 += w; cx1 += w * Vh[(size_t)i1 * DMODEL]; }
        if (s2 >= thr) { float w = __expf(s2 - mx); den2 += w; cx2 += w * Vh[(size_t)i2 * DMODEL]; }
        if (s3 >= thr) { float w = __expf(s3 - mx); den3 += w; cx3 += w * Vh[(size_t)i3 * DMODEL]; }
    }
    for (; e < cnt; ++e) {
        float s0 = lval[e];
        if (s0 >= thr) { float w = __expf(s0 - mx); den0 += w; cx0 += w * Vh[(size_t)lidx[e] * DMODEL]; }
    }
    float den = (den0 + den1) + (den2 + den3);
    float cx  = (cx0 + cx1) + (cx2 + cx3);
    CTX[(size_t)qglob * DMODEL + h * DH + lane] = cx / den;
}

// grid (NQ/QB, H), 512 threads = 16 warps.
// Score phase: bf16-split mma.sync; K arrives pre-converted (g_Kc) via
// cp.async into double-buffered pitched smem chunks (conflict-free frags).
// Per-query stats fused into score phase. Scores stored sc[key][q] pitch SCP.
__global__ __launch_bounds__(512, 1) void attn_kernel(
    const float* __restrict__ Q, const __nv_bfloat16* __restrict__ Kc,
    const float* __restrict__ V, float* __restrict__ CTX)
{
    extern __shared__ __align__(16) char smraw[];
    float* sc = (float*)smraw;                                  // M*SCP floats
    __nv_bfloat16* ks = (__nv_bfloat16*)(sc + M * SCP);         // 2 * CHUNK*KBP halves
    float* qs   = (float*)(ks + 2 * CHUNK * KBP);               // QB*32
    float* ssum = qs + QB * 32;                                 // QB*16
    float* ssq  = ssum + QB * 16;                               // QB*16
    float* smx  = ssq + QB * 16;                                // QB*16
    float* lval = (float*)ks;                                   // alias (score phase done)
    int*   lidx = (int*)(lval + QB * LIST_MAX);

    const int tid = threadIdx.x, lane = tid & 31, w = tid >> 5;
    const int h = blockIdx.y;
    const int qblock = blockIdx.x * QB;
    const int g = lane >> 2, tq = lane & 3;

    // load Q tile, scaled by 1/sqrt(DH)
    const float scale = 0.17677669529663687f;
    for (int i = tid; i < QB * 32; i += 512) {
        int ql = i >> 5, d = i & 31;
        qs[i] = Q[(size_t)(qblock + ql) * DMODEL + h * DH + d] * scale;
    }
    __syncthreads();

    // A fragments (bf16 hi/lo); rows = queries, k = dims
    unsigned ah[2][4], al[2][4];
    #pragma unroll
    for (int s = 0; s < 2; ++s) {
        int cb = s * 16 + tq * 2;
        split2(qs[g * 32 + cb],           qs[g * 32 + cb + 1],       ah[s][0], al[s][0]);
        split2(qs[(g + 8) * 32 + cb],     qs[(g + 8) * 32 + cb + 1], ah[s][1], al[s][1]);
        split2(qs[g * 32 + cb + 8],       qs[g * 32 + cb + 9],       ah[s][2], al[s][2]);
        split2(qs[(g + 8) * 32 + cb + 8], qs[(g + 8) * 32 + cb + 9], ah[s][3], al[s][3]);
    }

    // cp.async segment mapping: chunk = 2048 x 16B segs; thread does 4.
    const __nv_bfloat16* Kh = Kc + (size_t)h * M * 64;
    unsigned ks_base = (unsigned)__cvta_generic_to_shared(ks);

    // prologue: chunk 0 -> buf 0
    #pragma unroll
    for (int r = 0; r < 4; ++r) {
        int s = tid + 512 * r;
        int key = s >> 3, part = s & 7;
        cpa16(ks_base + key * 144 + part * 16,
              Kh + ((size_t)key * 64 + part * 8));
    }
    CPA_COMMIT();

    float sum_a = 0.f, sq_a = 0.f, mx_a = -3.3e38f;
    float sum_b = 0.f, sq_b = 0.f, mx_b = -3.3e38f;

    #pragma unroll 1
    for (int c = 0; c < NCHUNK; ++c) {
        if (c + 1 < NCHUNK) {
            unsigned dbase = ks_base + ((c + 1) & 1) * (CHUNK * KBP * 2);
            const __nv_bfloat16* src = Kh + (size_t)(c + 1) * CHUNK * 64;
            #pragma unroll
            for (int r = 0; r < 4; ++r) {
                int s = tid + 512 * r;
                int key = s >> 3, part = s & 7;
                cpa16(dbase + key * 144 + part * 16,
                      src + ((size_t)key * 64 + part * 8));
            }
            CPA_COMMIT();
            CPA_WAIT(1);
        } else {
            CPA_WAIT(0);
        }
        __syncthreads();  // chunk c resident in buf[c&1]

        const __nv_bfloat16* kb = ks + (c & 1) * (CHUNK * KBP);
        #pragma unroll
        for (int nt = 0; nt < 2; ++nt) {
            float c0 = 0.f, c1 = 0.f, c2 = 0.f, c3 = 0.f;
            const __nv_bfloat16* krp = kb + (w * 16 + nt * 8 + g) * KBP;
            #pragma unroll
            for (int s = 0; s < 2; ++s) {
                int ko = s * 16 + tq * 2;
                unsigned b0h = *(const unsigned*)&krp[ko];
                unsigned b1h = *(const unsigned*)&krp[ko + 8];
                unsigned b0l = *(const unsigned*)&krp[32 + ko];
                unsigned b1l = *(const unsigned*)&krp[32 + ko + 8];
                mma16816(c0, c1, c2, c3, ah[s][0], ah[s][1], ah[s][2], ah[s][3], b0h, b1h);
                mma16816(c0, c1, c2, c3, ah[s][0], ah[s][1], ah[s][2], ah[s][3], b0l, b1l);
                mma16816(c0, c1, c2, c3, al[s][0], al[s][1], al[s][2], al[s][3], b0h, b1h);
            }
            int gk = c * CHUNK + w * 16 + nt * 8 + tq * 2;
            sc[gk * SCP + g]           = c0;
            sc[(gk + 1) * SCP + g]     = c1;
            sc[gk * SCP + g + 8]       = c2;
            sc[(gk + 1) * SCP + g + 8] = c3;
            // fused stats: c0,c1 -> query g ; c2,c3 -> query g+8
            sum_a += c0 + c1; sq_a += c0 * c0 + c1 * c1;
            mx_a = fmaxf(mx_a, fmaxf(c0, c1));
            sum_b += c2 + c3; sq_b += c2 * c2 + c3 * c3;
            mx_b = fmaxf(mx_b, fmaxf(c2, c3));
        }
        __syncthreads();  // compute done before buf[c&1] is overwritten (iter c+1 issues copy c+2)
    }

    // combine stats over tq quad (lane bits 0..1), then store per-warp partials
    #pragma unroll
    for (int o = 1; o < 4; o <<= 1) {
        sum_a += __shfl_xor_sync(0xffffffffu, sum_a, o);
        sq_a  += __shfl_xor_sync(0xffffffffu, sq_a, o);
        mx_a   = fmaxf(mx_a, __shfl_xor_sync(0xffffffffu, mx_a, o));
        sum_b += __shfl_xor_sync(0xffffffffu, sum_b, o);
        sq_b  += __shfl_xor_sync(0xffffffffu, sq_b, o);
        mx_b   = fmaxf(mx_b, __shfl_xor_sync(0xffffffffu, mx_b, o));
    }
    if (tq == 0) {
        ssum[g * 16 + w] = sum_a;        ssq[g * 16 + w] = sq_a;        smx[g * 16 + w] = mx_a;
        ssum[(g + 8) * 16 + w] = sum_b;  ssq[(g + 8) * 16 + w] = sq_b;  smx[(g + 8) * 16 + w] = mx_b;
    }
    __syncthreads();  // scores + stats complete; ks dead -> lists alias it

    // selection: one warp per query
    const int q = w;
    float sum = (lane < 16) ? ssum[q * 16 + lane] : 0.f;
    float sq  = (lane < 16) ? ssq[q * 16 + lane]  : 0.f;
    float mx  = (lane < 16) ? smx[q * 16 + lane]  : -3.3e38f;
    sum = wredsum(sum); sq = wredsum(sq); mx = wredmax(mx);

    process_query(qblock + q, h, sc + q, lval + q * LIST_MAX,
                  lidx + q * LIST_MAX, sum, sq, mx, V, CTX, lane);
}

// ---------------- launch ----------------
extern "C" void kernel_launch(void* const* d_in, const int* in_sizes, int n_in,
                              void* d_out, int out_size)
{
    const float* x   = (const float*)d_in[0];
    const float* Ep  = (const float*)d_in[1];
    const float* Em  = (const float*)d_in[2];
    const float* Wq  = (const float*)d_in[3];
    const float* bq  = (const float*)d_in[4];
    const float* Wk  = (const float*)d_in[5];
    const float* bk  = (const float*)d_in[6];
    const float* Wv  = (const float*)d_in[7];
    const float* bv  = (const float*)d_in[8];
    const float* Wo  = (const float*)d_in[9];
    const float* bo  = (const float*)d_in[10];
    const float* W1  = (const float*)d_in[11];
    const float* b1  = (const float*)d_in[12];
    const float* W2  = (const float*)d_in[13];
    const float* b2  = (const float*)d_in[14];
    const float* g1  = (const float*)d_in[15];
    const float* be1 = (const float*)d_in[16];
    const float* g2  = (const float*)d_in[17];
    const float* be2 = (const float*)d_in[18];
    float* out = (float*)d_out;

    float *Qp, *Kp, *Vp, *CTXp, *ATTp, *X1p, *Hp, *FFp;
    __nv_bfloat16* Kcp;
    cudaGetSymbolAddress((void**)&Qp,  g_Q);
    cudaGetSymbolAddress((void**)&Kp,  g_K);
    cudaGetSymbolAddress((void**)&Vp,  g_V);
    cudaGetSymbolAddress((void**)&CTXp, g_CTX);
    cudaGetSymbolAddress((void**)&ATTp, g_ATT);
    cudaGetSymbolAddress((void**)&X1p, g_X1);
    cudaGetSymbolAddress((void**)&Hp,  g_HB);
    cudaGetSymbolAddress((void**)&FFp, g_FF);
    cudaGetSymbolAddress((void**)&Kcp, g_Kc);

    dim3 gq(NQ / 128, 2), gkv(M / 128, 2);
    sgemm_nt<0><<<gq, 256>>>(x, Wq, bq, Qp, NQ);
    sgemm_nt<0><<<gkv, 256>>>(Ep, Wk, bk, Kp, M);
    sgemm_nt<0><<<gkv, 256>>>(Em, Wv, bv, Vp, M);
    convK<<<(M * H) / 256, 256>>>(Kp, Kcp);

    size_t smem = (size_t)M * SCP * 4                 // sc
                + 2 * (size_t)CHUNK * KBP * 2         // K double buffer
                + QB * 32 * 4                         // qs
                + 3 * QB * 16 * 4;                    // stats
    cudaFuncSetAttribute(attn_kernel, cudaFuncAttributeMaxDynamicSharedMemorySize, (int)smem);
    attn_kernel<<<dim3(NQ / QB, H), 512, smem>>>(Qp, Kcp, Vp, CTXp);

    sgemm_nt<0><<<gq, 256>>>(CTXp, Wo, bo, ATTp, NQ);
    add_ln<<<NQ / 8, 256>>>(x, ATTp, g1, be1, X1p);
    sgemm_nt<1><<<gq, 256>>>(X1p, W1, b1, Hp, NQ);
    sgemm_nt<0><<<gq, 256>>>(Hp, W2, b2, FFp, NQ);
    add_ln<<<NQ / 8, 256>>>(X1p, FFp, g2, be2, out);
}